// round 17
// baseline (speedup 1.0000x reference)
#include <cuda_runtime.h>
#include <cuda_fp16.h>
#include <math_constants.h>

#define NFLOWS 8

// ---------------------------------------------------------------------------
// Device-global precomputed tables (no allocations anywhere — harness rule)
// Search tables fp32 (R14: fp16 compares cost more ALU than they save).
// Coef table fp16 (R15 WIN: halved dominant gather sectors; rel_err 1.65e-4).
// ---------------------------------------------------------------------------
__device__ float          g_hdr[NFLOWS][80];        // [0:64] sorted coarse thr, [64:73] wc, [73:76] c
__device__ float          g_sub[NFLOWS][4228];      // [s*65 + j] sorted sub-breakpoints (+INF pads)
__device__ __align__(16) unsigned short g_coefh[NFLOWS][4225][8];  // {al0..3, be0..3} fp16
__device__ float          g_L[9], g_bm[3], g_totc;

// ---------------------------------------------------------------------------
// Fused prep (identical to R15): grid (65, 8) x 128 threads. ALL FP32 math.
// ---------------------------------------------------------------------------
__global__ void k_prep(const float* __restrict__ L_tril, const float* __restrict__ bm,
                       const float* __restrict__ ls, const float* __restrict__ sh,
                       const float* __restrict__ P,  const float* __restrict__ ss,
                       const float* __restrict__ lm, const float* __restrict__ um,
                       const float* __restrict__ lls,
                       const float* __restrict__ W1, const float* __restrict__ b1,
                       const float* __restrict__ W2, const float* __restrict__ b2,
                       const float* __restrict__ W3, const float* __restrict__ b3) {
    __shared__ float  sW2[4096];
    __shared__ float  sa[64], sbv[64], sthr[64], sx[64];
    __shared__ int    srank[64], ssub[64];
    __shared__ float  sP[64], sQ[64];
    __shared__ unsigned char sin_[64], sact0[64];
    __shared__ float  sw3[4][64];
    __shared__ float  sb3v[4];

    const int s = blockIdx.x;   // 0..64
    const int f = blockIdx.y;
    const int t = threadIdx.x;

    for (int i = t; i < 4096; i += 128) sW2[i] = W2[f * 4096 + i];
    if (t < 64) {
        float a = W1[f * 64 + t], b = b1[f * 64 + t];
        sa[t] = a; sbv[t] = b;
        sx[t] = (a != 0.f) ? (-b / a) : CUDART_INF_F;  // raw thresholds (temp)
        sw3[0][t] = W3[f * 256 + t];
        sw3[1][t] = W3[f * 256 + 64 + t];
        sw3[2][t] = W3[f * 256 + 128 + t];
        sw3[3][t] = W3[f * 256 + 192 + t];
    }
    if (t >= 64 && t < 68) sb3v[t - 64] = b3[f * 4 + (t - 64)];
    __syncthreads();

    // redundant per-block rank sort of the 64 layer-1 breakpoints
    if (t < 64) {
        float tk = sx[t];
        int r = 0;
        for (int j = 0; j < 64; ++j) {
            float tj = sx[j];
            r += (tj < tk) || (tj == tk && j < t);
        }
        srank[t] = r;
        sthr[r] = tk;
    }
    __syncthreads();

    // block s==0 of each flow publishes the header (sorted thr + wc + c)
    if (s == 0) {
        if (t < 64) g_hdr[f][t] = sthr[t];
        if (t == 64) {
            float el[3], shv[3];
            for (int d = 0; d < 3; d++) { el[d] = expf(ls[f * 3 + d]); shv[d] = sh[f * 3 + d]; }
            float l[3][3], U[3][3];
            for (int aa = 0; aa < 3; aa++)
                for (int bb = 0; bb < 3; bb++) {
                    l[aa][bb] = (bb < aa ? lm[f * 9 + aa * 3 + bb] : (aa == bb ? 1.f : 0.f));
                    U[aa][bb] = (bb > aa ? um[f * 9 + aa * 3 + bb] : 0.f);
                }
            for (int d = 0; d < 3; d++) U[d][d] = ss[f * 3 + d] * expf(lls[f * 3 + d]);
            float A[3][3], Wm[3][3];
            for (int aa = 0; aa < 3; aa++)
                for (int bb = 0; bb < 3; bb++) {
                    float s2 = 0.f;
                    for (int q = 0; q < 3; q++) s2 += l[aa][q] * U[q][bb];
                    A[aa][bb] = s2;
                }
            for (int aa = 0; aa < 3; aa++)
                for (int bb = 0; bb < 3; bb++) {
                    float s2 = 0.f;
                    for (int q = 0; q < 3; q++) s2 += P[f * 9 + aa * 3 + q] * A[q][bb];
                    Wm[aa][bb] = s2;
                }
            for (int aa = 0; aa < 3; aa++) {
                float cs = 0.f;
                for (int bb = 0; bb < 3; bb++) {
                    float wcv = Wm[aa][bb] * el[bb];
                    g_hdr[f][64 + aa * 3 + bb] = wcv;
                    cs += wcv * shv[bb];
                }
                g_hdr[f][73 + aa] = cs;
            }
        }
        if (f == 0 && t == 65) {
            float Lt[3][3], cov[3][3];
            for (int aa = 0; aa < 3; aa++)
                for (int bb = 0; bb < 3; bb++)
                    Lt[aa][bb] = (bb <= aa ? L_tril[aa * 3 + bb] : 0.f) + (aa == bb ? 1e-6f : 0.f);
            for (int aa = 0; aa < 3; aa++)
                for (int bb = 0; bb < 3; bb++) {
                    float s2 = 0.f;
                    for (int q = 0; q < 3; q++) s2 += Lt[aa][q] * Lt[bb][q];
                    cov[aa][bb] = s2;
                }
            float L00 = sqrtf(cov[0][0]);
            float L10 = cov[1][0] / L00, L20 = cov[2][0] / L00;
            float L11 = sqrtf(cov[1][1] - L10 * L10);
            float L21 = (cov[2][1] - L20 * L10) / L11;
            float L22 = sqrtf(cov[2][2] - L20 * L20 - L21 * L21);
            float Lm[9] = {L00, 0.f, 0.f, L10, L11, 0.f, L20, L21, L22};
            for (int q = 0; q < 9; q++) g_L[q] = Lm[q];
            for (int q = 0; q < 3; q++) g_bm[q] = bm[q];
        }
        if (f == 0 && t == 66) {
            float tot = 0.f;
            for (int q = 0; q < NFLOWS * 3; q++) tot += ls[q] + lls[q];
            g_totc = tot;
        }
    }

    const float lo = (s == 0)  ? -CUDART_INF_F : sthr[s - 1];
    const float hi = (s == 64) ?  CUDART_INF_F : sthr[s];

    if (t < 64) {
        const int u = t;
        float Pd = 0.f, Qd = b2[f * 64 + u];
        for (int j = 0; j < 64; ++j) {
            float aj = sa[j];
            bool act = (aj > 0.f) ? (srank[j] < s)
                     : (aj < 0.f) ? (srank[j] >= s)
                                  : (sbv[j] > 0.f);
            if (act) {
                float w = sW2[u * 64 + j];
                Pd = fmaf(w, aj, Pd);
                Qd = fmaf(w, sbv[j], Qd);
            }
        }
        sP[u] = Pd; sQ[u] = Qd;
        float xu = (Pd != 0.f) ? (-Qd / Pd) : CUDART_INF_F;
        bool inside = (Pd != 0.f) && (xu > lo) && (xu < hi);
        sx[u]  = inside ? xu : CUDART_INF_F;
        sin_[u] = inside ? 1 : 0;
        bool a0;                                // active just above lo?
        if (Pd > 0.f)      a0 = (xu <= lo);
        else if (Pd < 0.f) a0 = (xu > lo);
        else               a0 = (Qd > 0.f);
        sact0[u] = a0 ? 1 : 0;
    }
    __syncthreads();
    if (t < 64) {
        float key = sx[t];
        int r = 0;
        for (int j = 0; j < 64; ++j) {
            float xj = sx[j];
            r += (xj < key) || (xj == key && j < t);
        }
        ssub[t] = r;
        g_sub[f][s * 65 + r] = key;               // sorted (INF pads at top)
        if (t == 0) g_sub[f][s * 65 + 64] = CUDART_INF_F;
    }
    __syncthreads();
    if (t < 65) {                                 // sub-segment j = t
        float al0 = 0.f, al1 = 0.f, al2 = 0.f, al3 = 0.f;
        float be0 = sb3v[0], be1 = sb3v[1], be2 = sb3v[2], be3 = sb3v[3];
        for (int u = 0; u < 64; ++u) {
            bool act = (sact0[u] != 0) != ((sin_[u] != 0) && (ssub[u] < t));
            if (act) {
                float Pu = sP[u], Qu = sQ[u];
                float w0 = sw3[0][u], w1 = sw3[1][u], w2 = sw3[2][u], w3v = sw3[3][u];
                al0 = fmaf(w0, Pu, al0); al1 = fmaf(w1, Pu, al1);
                al2 = fmaf(w2, Pu, al2); al3 = fmaf(w3v, Pu, al3);
                be0 = fmaf(w0, Qu, be0); be1 = fmaf(w1, Qu, be1);
                be2 = fmaf(w2, Qu, be2); be3 = fmaf(w3v, Qu, be3);
            }
        }
        int idx = s * 65 + t;
        __half2 p0 = __floats2half2_rn(al0, al1);
        __half2 p1 = __floats2half2_rn(al2, al3);
        __half2 p2 = __floats2half2_rn(be0, be1);
        __half2 p3 = __floats2half2_rn(be2, be3);
        uint4 pk;
        pk.x = *(unsigned int*)&p0;
        pk.y = *(unsigned int*)&p1;
        pk.z = *(unsigned int*)&p2;
        pk.w = *(unsigned int*)&p3;
        *((uint4*)g_coefh[f] + idx) = pk;
    }
}

// ---------------------------------------------------------------------------
// Main kernel: 512 thr/CTA, ONE sample/thread -> 262144 threads, ~55 warps/SM
// (was 13.8 — the R15 latency limiter; L1 now has 3x headroom post-fp16-coef).
// smem-staged fp32 search tables, two 6-step searches, one 16B fp16 coef gather.
// ---------------------------------------------------------------------------
__global__ __launch_bounds__(512)
void glow_main(const float* __restrict__ eps, float* __restrict__ out, int N) {
    __shared__ float sm[80 + 4228];

    const int tid = threadIdx.x;
    int gi = blockIdx.x * 512 + tid;
    const bool valid = gi < N;
    const int i = valid ? gi : (N - 1);

    const float L0 = g_L[0], L3 = g_L[3], L4 = g_L[4],
                L6 = g_L[6], L7 = g_L[7], L8 = g_L[8];
    const float m0 = g_bm[0], m1 = g_bm[1], m2 = g_bm[2];

    float e0 = eps[3 * i], e1 = eps[3 * i + 1], e2 = eps[3 * i + 2];
    float z0 = m0 + L0 * e0;
    float z1 = m1 + L3 * e0 + L4 * e1;
    float z2 = m2 + L6 * e0 + L7 * e1 + L8 * e2;
    float ld = 0.f;

    for (int f = 0; f < NFLOWS; ++f) {
        __syncthreads();                       // protect smem from prior flow readers
        if (tid < 20) ((float4*)sm)[tid] = ((const float4*)g_hdr[f])[tid];
        {
            float4* ds = (float4*)(sm + 80);
            const float4* s4 = (const float4*)g_sub[f];
            #pragma unroll
            for (int q = 0; q < 2; ++q) ds[tid + q * 512] = s4[tid + q * 512];
            if (tid < 33) ds[tid + 1024] = s4[tid + 1024];
        }
        __syncthreads();

        // folded actnorm + 1x1 conv
        const float* wcp = sm + 64;
        {
            float n0 = wcp[9]  + wcp[0] * z0 + wcp[1] * z1 + wcp[2] * z2;
            float n1 = wcp[10] + wcp[3] * z0 + wcp[4] * z1 + wcp[5] * z2;
            float n2 = wcp[11] + wcp[6] * z0 + wcp[7] * z1 + wcp[8] * z2;
            z0 = n0; z1 = n1; z2 = n2;
        }

        // coarse segment rank in [0,64]
        const float* thr = sm;
        int sS = 0;
        #pragma unroll
        for (int st = 32; st; st >>= 1)
            if (thr[sS + st - 1] < z0) sS += st;
        if (sS == 63 && thr[63] < z0) sS = 64;

        // fine sub-segment rank in [0,64]
        const float* sub = sm + 80 + sS * 65;
        int jS = 0;
        #pragma unroll
        for (int st = 32; st; st >>= 1)
            if (sub[jS + st - 1] < z0) jS += st;
        if (jS == 63 && sub[63] < z0) jS = 64;

        // exact affine MLP output: ONE 16B fp16 coef gather
        uint4 ce = __ldg((const uint4*)g_coefh[f] + (sS * 65 + jS));
        float2 a01 = __half22float2(*(__half2*)&ce.x);
        float2 a23 = __half22float2(*(__half2*)&ce.y);
        float2 b01 = __half22float2(*(__half2*)&ce.z);
        float2 b23 = __half22float2(*(__half2*)&ce.w);

        float o0 = fmaf(a01.x, z0, b01.x), o1 = fmaf(a01.y, z0, b01.y);
        float o2 = fmaf(a23.x, z0, b23.x), o3 = fmaf(a23.y, z0, b23.y);
        z1 = fmaf(z1, __expf(o2), o0);
        z2 = fmaf(z2, __expf(o3), o1);
        ld += o2 + o3;
    }

    if (valid) {
        out[3 * i]     = z0;
        out[3 * i + 1] = __expf(z1);
        out[3 * i + 2] = __expf(z2);
        out[3 * N + i] = ld + g_totc + z1 + z2;
    }
}

// ---------------------------------------------------------------------------
// Launch. Inputs (metadata order): eps, L_tril, base_mean, an_log_scale,
// an_shift, perm_p, sign_s, lu_l, lu_u, lu_log_s, W1, b1, W2, b2, W3, b3
// Output: [z_t (N,3) row-major][log_det (N)] float32 (layout verified R4..R15)
// ---------------------------------------------------------------------------
extern "C" void kernel_launch(void* const* d_in, const int* in_sizes, int n_in,
                              void* d_out, int out_size) {
    const float* eps    = (const float*)d_in[0];
    const float* L_tril = (const float*)d_in[1];
    const float* bm     = (const float*)d_in[2];
    const float* an_ls  = (const float*)d_in[3];
    const float* an_sh  = (const float*)d_in[4];
    const float* perm   = (const float*)d_in[5];
    const float* ss     = (const float*)d_in[6];
    const float* lu_l   = (const float*)d_in[7];
    const float* lu_u   = (const float*)d_in[8];
    const float* lu_ls  = (const float*)d_in[9];
    const float* W1     = (const float*)d_in[10];
    const float* b1     = (const float*)d_in[11];
    const float* W2     = (const float*)d_in[12];
    const float* b2     = (const float*)d_in[13];
    const float* W3     = (const float*)d_in[14];
    const float* b3     = (const float*)d_in[15];
    float* out = (float*)d_out;

    int N = in_sizes[0] / 3;

    k_prep<<<dim3(65, NFLOWS), 128>>>(L_tril, bm, an_ls, an_sh, perm, ss,
                                      lu_l, lu_u, lu_ls, W1, b1, W2, b2, W3, b3);
    glow_main<<<(N + 511) / 512, 512>>>(eps, out, N);
}